// round 14
// baseline (speedup 1.0000x reference)
#include <cuda_runtime.h>
#include <math.h>
#include <stdint.h>

// ---------------- problem constants ----------------
#define S_LEN   2048
#define BATCH   2
#define DIM_    2048
#define NH      16
#define NKV     4
#define HD      128
#define MROWS   (BATCH * S_LEN)      // 4096

// ---------------- device scratch (static, allocation-free) ----------------
__device__ float g_q[(size_t)MROWS * NH * HD];      // [4096][2048]
__device__ float g_k[(size_t)MROWS * NKV * HD];     // [4096][512]
__device__ float g_v[(size_t)MROWS * NKV * HD];     // [4096][512]
__device__ float g_attn[(size_t)MROWS * DIM_];      // [4096][2048]

// ---------------- tf32 helpers ----------------
__device__ __forceinline__ uint32_t f2tf32(float x) {
    uint32_t r;
    asm("cvt.rna.tf32.f32 %0, %1;" : "=r"(r) : "f"(x));
    return r;
}

__device__ __forceinline__ void mma_tf32(float c[4],
    uint32_t a0, uint32_t a1, uint32_t a2, uint32_t a3,
    uint32_t b0, uint32_t b1)
{
    asm volatile(
        "mma.sync.aligned.m16n8k8.row.col.f32.tf32.tf32.f32 "
        "{%0,%1,%2,%3}, {%4,%5,%6,%7}, {%8,%9}, {%0,%1,%2,%3};"
        : "+f"(c[0]), "+f"(c[1]), "+f"(c[2]), "+f"(c[3])
        : "r"(a0), "r"(a1), "r"(a2), "r"(a3), "r"(b0), "r"(b1));
}

// =====================================================================
// TF32 tensor-core GEMM, ping-pong double-buffered smem (1 sync/iter).
// C[M,N] = A[M,K] @ B[K,N], row-major fp32 in/out.
// BM=BN=128, BK=16, 256 threads (8 warps), warp tile 64x32.
// =====================================================================
#define SMS 132   // smem row stride (132 % 32 == 4 -> conflict-free frag LDS)

__global__ __launch_bounds__(256) void gemm_tf32(
    const float* __restrict__ A, const float* __restrict__ B,
    float* __restrict__ C, int M, int N, int K)
{
    __shared__ uint32_t As[2][16][SMS];   // As[st][k][m], tf32 bits
    __shared__ uint32_t Bs[2][16][SMS];   // Bs[st][k][n], tf32 bits

    const int tid  = threadIdx.x;
    const int lane = tid & 31;
    const int warp = tid >> 5;
    const int wm   = (warp >> 2) * 64;
    const int wn   = (warp & 3) * 32;
    const int grp  = lane >> 2;
    const int qd   = lane & 3;

    const int brow = blockIdx.y * 128;
    const int bcol = blockIdx.x * 128;

    const int rowA = tid >> 2;           // 0..63 (second: +64)
    const int colA = (tid & 3) * 4;      // 0,4,8,12
    const int rowB = tid >> 5;           // 0..7  (second: +8)
    const int colB = (tid & 31) * 4;     // 0..124

    const float* Ap0 = A + (size_t)(brow + rowA)      * K + colA;
    const float* Ap1 = A + (size_t)(brow + rowA + 64) * K + colA;
    const float* Bp0 = B + (size_t)rowB       * N + bcol + colB;
    const float* Bp1 = B + (size_t)(rowB + 8) * N + bcol + colB;

    float acc[4][4][4];
#pragma unroll
    for (int i = 0; i < 4; ++i)
#pragma unroll
        for (int j = 0; j < 4; ++j)
#pragma unroll
            for (int r = 0; r < 4; ++r) acc[i][j][r] = 0.f;

    const int nk = K >> 4;

    float4 pa0 = *(const float4*)Ap0;
    float4 pa1 = *(const float4*)Ap1;
    float4 pb0 = *(const float4*)Bp0;
    float4 pb1 = *(const float4*)Bp1;

#define GEMM_STORE_STAGE(st)                                             \
    do {                                                                 \
        As[st][colA + 0][rowA]      = f2tf32(pa0.x);                     \
        As[st][colA + 1][rowA]      = f2tf32(pa0.y);                     \
        As[st][colA + 2][rowA]      = f2tf32(pa0.z);                     \
        As[st][colA + 3][rowA]      = f2tf32(pa0.w);                     \
        As[st][colA + 0][rowA + 64] = f2tf32(pa1.x);                     \
        As[st][colA + 1][rowA + 64] = f2tf32(pa1.y);                     \
        As[st][colA + 2][rowA + 64] = f2tf32(pa1.z);                     \
        As[st][colA + 3][rowA + 64] = f2tf32(pa1.w);                     \
        Bs[st][rowB][colB + 0]      = f2tf32(pb0.x);                     \
        Bs[st][rowB][colB + 1]      = f2tf32(pb0.y);                     \
        Bs[st][rowB][colB + 2]      = f2tf32(pb0.z);                     \
        Bs[st][rowB][colB + 3]      = f2tf32(pb0.w);                     \
        Bs[st][rowB + 8][colB + 0]  = f2tf32(pb1.x);                     \
        Bs[st][rowB + 8][colB + 1]  = f2tf32(pb1.y);                     \
        Bs[st][rowB + 8][colB + 2]  = f2tf32(pb1.z);                     \
        Bs[st][rowB + 8][colB + 3]  = f2tf32(pb1.w);                     \
    } while (0)

    // prologue: stage 0 holds t=0; regs hold t=1
    GEMM_STORE_STAGE(0);
    if (nk > 1) {
        pa0 = *(const float4*)(Ap0 + 16);
        pa1 = *(const float4*)(Ap1 + 16);
        pb0 = *(const float4*)(Bp0 + (size_t)16 * N);
        pb1 = *(const float4*)(Bp1 + (size_t)16 * N);
    }
    __syncthreads();

    for (int t = 0; t < nk; ++t) {
        const int cs = t & 1;
        if (t + 1 < nk) {
            GEMM_STORE_STAGE(cs ^ 1);        // regs hold data for t+1
        }
        if (t + 2 < nk) {
            pa0 = *(const float4*)(Ap0 + (size_t)(t + 2) * 16);
            pa1 = *(const float4*)(Ap1 + (size_t)(t + 2) * 16);
            pb0 = *(const float4*)(Bp0 + (size_t)(t + 2) * 16 * N);
            pb1 = *(const float4*)(Bp1 + (size_t)(t + 2) * 16 * N);
        }

#pragma unroll
        for (int ks = 0; ks < 16; ks += 8) {
            uint32_t af[4][4], bf[4][2];
#pragma unroll
            for (int mt = 0; mt < 4; ++mt) {
                int m0 = wm + mt * 16 + grp;
                af[mt][0] = As[cs][ks + qd][m0];
                af[mt][1] = As[cs][ks + qd][m0 + 8];
                af[mt][2] = As[cs][ks + 4 + qd][m0];
                af[mt][3] = As[cs][ks + 4 + qd][m0 + 8];
            }
#pragma unroll
            for (int nt = 0; nt < 4; ++nt) {
                int n0 = wn + nt * 8 + grp;
                bf[nt][0] = Bs[cs][ks + qd][n0];
                bf[nt][1] = Bs[cs][ks + 4 + qd][n0];
            }
#pragma unroll
            for (int mt = 0; mt < 4; ++mt)
#pragma unroll
                for (int nt = 0; nt < 4; ++nt)
                    mma_tf32(acc[mt][nt],
                             af[mt][0], af[mt][1], af[mt][2], af[mt][3],
                             bf[nt][0], bf[nt][1]);
        }
        __syncthreads();
    }

#pragma unroll
    for (int mt = 0; mt < 4; ++mt) {
#pragma unroll
        for (int nt = 0; nt < 4; ++nt) {
            int r = brow + wm + mt * 16 + grp;
            int c = bcol + wn + nt * 8 + 2 * qd;
            float2 lo = {acc[mt][nt][0], acc[mt][nt][1]};
            float2 hi = {acc[mt][nt][2], acc[mt][nt][3]};
            *(float2*)&C[(size_t)r * N + c]       = lo;
            *(float2*)&C[(size_t)(r + 8) * N + c] = hi;
        }
    }
#undef GEMM_STORE_STAGE
}

// =====================================================================
// RoPE, in place. data: [MROWS][heads*128].
// =====================================================================
__global__ void rope_kernel(float* __restrict__ data, int heads, int total)
{
    int idx = blockIdx.x * blockDim.x + threadIdx.x;
    if (idx >= total) return;
    int j   = idx & 63;
    int t2  = idx >> 6;
    int h   = t2 % heads;
    int row = t2 / heads;
    int s   = row & (S_LEN - 1);

    float inv = exp2f((float)j * (-13.287712379549449f / 64.0f));
    float ang = (float)s * inv;
    float sn, cs;
    sincosf(ang, &sn, &cs);

    float* p = data + (size_t)row * heads * HD + (size_t)h * HD;
    float x1 = p[j];
    float x2 = p[j + 64];
    p[j]      = x1 * cs - x2 * sn;
    p[j + 64] = x2 * cs + x1 * sn;
}

// =====================================================================
// Flash attention with tf32 tensor-core MMAs, causal, GQA.
// Grid: (S/64, NH, BATCH). Block: 256 threads (8 warps).
// QK^T: warp tile 16x32 (warps 4x2). PV: warp tile 16x64 (warps 4x2).
// Online softmax stays fp32 in smem.
//   sQ [64][132] tf32 bits, sK [64][132] tf32 bits, sV [64][136] tf32 bits,
//   sP [64][68] fp32, stats 3x64.  (pitches chosen for conflict-free frags)
// =====================================================================
#define AQ_P 132
#define AV_P 136
#define AP_P 68
#define ATTN_SMEM_WORDS (64*AQ_P + 64*AQ_P + 64*AV_P + 64*AP_P + 192)
#define ATTN_SMEM_BYTES (ATTN_SMEM_WORDS * 4)

__global__ __launch_bounds__(256) void attn_mma_kernel(
    const float* __restrict__ Q, const float* __restrict__ K,
    const float* __restrict__ V, float* __restrict__ O)
{
    extern __shared__ uint32_t sm[];
    uint32_t* sQ = sm;                        // [64][132]
    uint32_t* sK = sQ + 64 * AQ_P;            // [64][132]
    uint32_t* sV = sK + 64 * AQ_P;            // [64][136]
    float*    sP = (float*)(sV + 64 * AV_P);  // [64][68]
    float*    rM = sP + 64 * AP_P;
    float*    rL = rM + 64;
    float*    rF = rL + 64;

    const int tid  = threadIdx.x;
    const int lane = tid & 31;
    const int warp = tid >> 5;
    const int grp  = lane >> 2;       // 0..7
    const int qd   = lane & 3;        // 0..3
    const int wr   = warp >> 1;       // 0..3  (m-tile)
    const int wc   = warp & 1;        // 0..1
    const int m0   = wr * 16;

    const int qt = blockIdx.x;
    const int h  = blockIdx.y;
    const int b  = blockIdx.z;
    const int hk = h >> 2;            // GQA repeat_interleave
    const int q0 = qt * 64;

    const size_t qbase  = ((size_t)b * S_LEN + q0) * (NH * HD) + (size_t)h * HD;
    const size_t kvbase = ((size_t)b * S_LEN) * (NKV * HD) + (size_t)hk * HD;

    // ---- load Q tile (cvt to tf32 bits) ----
    for (int f = tid; f < 2048; f += 256) {
        int r = f >> 5;               // 0..63
        int c = (f & 31) * 4;         // 0..124
        float4 v = *(const float4*)(Q + qbase + (size_t)r * (NH * HD) + c);
        uint4 u = {f2tf32(v.x), f2tf32(v.y), f2tf32(v.z), f2tf32(v.w)};
        *(uint4*)&sQ[r * AQ_P + c] = u;
    }
    if (tid < 64) { rM[tid] = -INFINITY; rL[tid] = 0.f; }

    float o_acc[8][4];
#pragma unroll
    for (int i = 0; i < 8; ++i)
#pragma unroll
        for (int j = 0; j < 4; ++j) o_acc[i][j] = 0.f;

    const float scale = 0.08838834764831845f;  // 1/sqrt(128)
    const int ntiles = qt + 1;

    for (int t = 0; t < ntiles; ++t) {
        const int k0 = t * 64;
        __syncthreads();  // prev PV done (covers Q/stats init at t=0)

        // ---- load K, V tiles ----
        for (int f = tid; f < 2048; f += 256) {
            int r = f >> 5, c = (f & 31) * 4;
            float4 v = *(const float4*)(K + kvbase + (size_t)(k0 + r) * (NKV * HD) + c);
            uint4 u = {f2tf32(v.x), f2tf32(v.y), f2tf32(v.z), f2tf32(v.w)};
            *(uint4*)&sK[r * AQ_P + c] = u;
        }
        for (int f = tid; f < 2048; f += 256) {
            int r = f >> 5, c = (f & 31) * 4;
            float4 v = *(const float4*)(V + kvbase + (size_t)(k0 + r) * (NKV * HD) + c);
            uint4 u = {f2tf32(v.x), f2tf32(v.y), f2tf32(v.z), f2tf32(v.w)};
            *(uint4*)&sV[r * AV_P + c] = u;
        }
        __syncthreads();

        // ---- S = Q @ K^T : warp tile 16x32, K-dim 128 (16 mma k-steps) ----
        float s_acc[4][4];
#pragma unroll
        for (int nt = 0; nt < 4; ++nt)
#pragma unroll
            for (int r = 0; r < 4; ++r) s_acc[nt][r] = 0.f;

#pragma unroll
        for (int ks = 0; ks < 16; ++ks) {
            const int kk = ks * 8;
            uint32_t a0 = sQ[(m0 + grp)     * AQ_P + kk + qd];
            uint32_t a1 = sQ[(m0 + grp + 8) * AQ_P + kk + qd];
            uint32_t a2 = sQ[(m0 + grp)     * AQ_P + kk + qd + 4];
            uint32_t a3 = sQ[(m0 + grp + 8) * AQ_P + kk + qd + 4];
#pragma unroll
            for (int nt = 0; nt < 4; ++nt) {
                int n = wc * 32 + nt * 8 + grp;
                uint32_t b0 = sK[n * AQ_P + kk + qd];
                uint32_t b1 = sK[n * AQ_P + kk + qd + 4];
                mma_tf32(s_acc[nt], a0, a1, a2, a3, b0, b1);
            }
        }

        // ---- write S to sP with scale + causal mask ----
        const bool dg = (k0 == q0);
        const int r0 = m0 + grp, r1 = m0 + grp + 8;
#pragma unroll
        for (int nt = 0; nt < 4; ++nt) {
            int nc = wc * 32 + nt * 8 + 2 * qd;
            float v0 = s_acc[nt][0] * scale;
            float v1 = s_acc[nt][1] * scale;
            float v2 = s_acc[nt][2] * scale;
            float v3 = s_acc[nt][3] * scale;
            if (dg) {
                if (nc     > r0) v0 = -INFINITY;
                if (nc + 1 > r0) v1 = -INFINITY;
                if (nc     > r1) v2 = -INFINITY;
                if (nc + 1 > r1) v3 = -INFINITY;
            }
            sP[r0 * AP_P + nc]     = v0;
            sP[r0 * AP_P + nc + 1] = v1;
            sP[r1 * AP_P + nc]     = v2;
            sP[r1 * AP_P + nc + 1] = v3;
        }
        __syncthreads();

        // ---- online softmax: 4 threads per row, 16 cols each ----
        {
            int row = tid >> 2, seg = tid & 3;
            float* pr = &sP[row * AP_P + seg * 16];
            float m_old = rM[row];
            float ml = -INFINITY;
#pragma unroll
            for (int i = 0; i < 16; ++i) ml = fmaxf(ml, pr[i]);
            ml = fmaxf(ml, __shfl_xor_sync(0xffffffffu, ml, 1));
            ml = fmaxf(ml, __shfl_xor_sync(0xffffffffu, ml, 2));
            float m_new = fmaxf(m_old, ml);
            float ls = 0.f;
#pragma unroll
            for (int i = 0; i < 16; ++i) {
                float p = __expf(pr[i] - m_new);
                pr[i] = p;
                ls += p;
            }
            ls += __shfl_xor_sync(0xffffffffu, ls, 1);
            ls += __shfl_xor_sync(0xffffffffu, ls, 2);
            if (seg == 0) {
                float fac = __expf(m_old - m_new);
                rF[row] = fac;
                rL[row] = rL[row] * fac + ls;
                rM[row] = m_new;
            }
        }
        __syncthreads();

        // ---- rescale O, accumulate O += P @ V : warp tile 16x64, K=64 ----
        const float fr0 = rF[m0 + grp];
        const float fr1 = rF[m0 + grp + 8];
#pragma unroll
        for (int nt = 0; nt < 8; ++nt) {
            o_acc[nt][0] *= fr0; o_acc[nt][1] *= fr0;
            o_acc[nt][2] *= fr1; o_acc[nt][3] *= fr1;
        }

#pragma unroll
        for (int ks = 0; ks < 8; ++ks) {
            const int kk = ks * 8;
            uint32_t a0 = f2tf32(sP[(m0 + grp)     * AP_P + kk + qd]);
            uint32_t a1 = f2tf32(sP[(m0 + grp + 8) * AP_P + kk + qd]);
            uint32_t a2 = f2tf32(sP[(m0 + grp)     * AP_P + kk + qd + 4]);
            uint32_t a3 = f2tf32(sP[(m0 + grp + 8) * AP_P + kk + qd + 4]);
#pragma unroll
            for (int nt = 0; nt < 8; ++nt) {
                int n = wc * 64 + nt * 8 + grp;
                uint32_t b0 = sV[(kk + qd)     * AV_P + n];
                uint32_t b1 = sV[(kk + qd + 4) * AV_P + n];
                mma_tf32(o_acc[nt], a0, a1, a2, a3, b0, b1);
            }
        }
    }

    // ---- normalize, write out ----
    const float inv0 = 1.f / rL[m0 + grp];
    const float inv1 = 1.f / rL[m0 + grp + 8];
    const size_t ro0 = ((size_t)b * S_LEN + q0 + m0 + grp)     * DIM_ + (size_t)h * HD;
    const size_t ro1 = ((size_t)b * S_LEN + q0 + m0 + grp + 8) * DIM_ + (size_t)h * HD;
#pragma unroll
    for (int nt = 0; nt < 8; ++nt) {
        int c = wc * 64 + nt * 8 + 2 * qd;
        float2 lo = {o_acc[nt][0] * inv0, o_acc[nt][1] * inv0};
        float2 hi = {o_acc[nt][2] * inv1, o_acc[nt][3] * inv1};
        *(float2*)&O[ro0 + c] = lo;
        *(float2*)&O[ro1 + c] = hi;
    }
}

// =====================================================================
// kernel_launch: x, wq, wk, wv, wo  (metadata order)
// =====================================================================
extern "C" void kernel_launch(void* const* d_in, const int* in_sizes, int n_in,
                              void* d_out, int out_size)
{
    const float* x  = (const float*)d_in[0];
    const float* wq = (const float*)d_in[1];
    const float* wk = (const float*)d_in[2];
    const float* wv = (const float*)d_in[3];
    const float* wo = (const float*)d_in[4];
    float* out = (float*)d_out;

    float *q, *k, *v, *attn;
    cudaGetSymbolAddress((void**)&q,    g_q);
    cudaGetSymbolAddress((void**)&k,    g_k);
    cudaGetSymbolAddress((void**)&v,    g_v);
    cudaGetSymbolAddress((void**)&attn, g_attn);

    // QKV projections (tf32 tensor cores, ping-pong pipelined)
    gemm_tf32<<<dim3(DIM_ / 128, MROWS / 128), 256>>>(x, wq, q, MROWS, DIM_, DIM_);
    gemm_tf32<<<dim3((NKV * HD) / 128, MROWS / 128), 256>>>(x, wk, k, MROWS, NKV * HD, DIM_);
    gemm_tf32<<<dim3((NKV * HD) / 128, MROWS / 128), 256>>>(x, wv, v, MROWS, NKV * HD, DIM_);

    // RoPE on Q and K
    {
        int totq = MROWS * NH * 64;
        rope_kernel<<<(totq + 255) / 256, 256>>>(q, NH, totq);
        int totk = MROWS * NKV * 64;
        rope_kernel<<<(totk + 255) / 256, 256>>>(k, NKV, totk);
    }

    // Flash attention (tf32 tensor cores)
    cudaFuncSetAttribute(attn_mma_kernel, cudaFuncAttributeMaxDynamicSharedMemorySize,
                         ATTN_SMEM_BYTES);
    attn_mma_kernel<<<dim3(S_LEN / 64, NH, BATCH), 256, ATTN_SMEM_BYTES>>>(q, k, v, attn);

    // Output projection
    gemm_tf32<<<dim3(DIM_ / 128, MROWS / 128), 256>>>(attn, wo, out, MROWS, DIM_, DIM_);
}

// round 15
// speedup vs baseline: 1.0021x; 1.0021x over previous
#include <cuda_runtime.h>
#include <math.h>
#include <stdint.h>

// ---------------- problem constants ----------------
#define S_LEN   2048
#define BATCH   2
#define DIM_    2048
#define NH      16
#define NKV     4
#define HD      128
#define MROWS   (BATCH * S_LEN)      // 4096

// ---------------- device scratch (static, allocation-free) ----------------
__device__ float g_q[(size_t)MROWS * NH * HD];      // [4096][2048]
__device__ float g_k[(size_t)MROWS * NKV * HD];     // [4096][512]
__device__ float g_v[(size_t)MROWS * NKV * HD];     // [4096][512]
__device__ float g_attn[(size_t)MROWS * DIM_];      // [4096][2048]

// ---------------- tf32 helpers ----------------
__device__ __forceinline__ uint32_t f2tf32(float x) {
    uint32_t r;
    asm("cvt.rna.tf32.f32 %0, %1;" : "=r"(r) : "f"(x));
    return r;
}

__device__ __forceinline__ void mma_tf32(float c[4],
    uint32_t a0, uint32_t a1, uint32_t a2, uint32_t a3,
    uint32_t b0, uint32_t b1)
{
    asm volatile(
        "mma.sync.aligned.m16n8k8.row.col.f32.tf32.tf32.f32 "
        "{%0,%1,%2,%3}, {%4,%5,%6,%7}, {%8,%9}, {%0,%1,%2,%3};"
        : "+f"(c[0]), "+f"(c[1]), "+f"(c[2]), "+f"(c[3])
        : "r"(a0), "r"(a1), "r"(a2), "r"(a3), "r"(b0), "r"(b1));
}

// =====================================================================
// TF32 tensor-core GEMM, ping-pong double-buffered smem (1 sync/iter).
// C[M,N] = A[M,K] @ B[K,N], row-major fp32 in/out.
// BM=BN=128, BK=16, 256 threads (8 warps), warp tile 64x32.
// =====================================================================
#define SMS 132   // smem row stride (132 % 32 == 4 -> conflict-free frag LDS)

__global__ __launch_bounds__(256) void gemm_tf32(
    const float* __restrict__ A, const float* __restrict__ B,
    float* __restrict__ C, int M, int N, int K)
{
    __shared__ uint32_t As[2][16][SMS];   // As[st][k][m], tf32 bits
    __shared__ uint32_t Bs[2][16][SMS];   // Bs[st][k][n], tf32 bits

    const int tid  = threadIdx.x;
    const int lane = tid & 31;
    const int warp = tid >> 5;
    const int wm   = (warp >> 2) * 64;
    const int wn   = (warp & 3) * 32;
    const int grp  = lane >> 2;
    const int qd   = lane & 3;

    const int brow = blockIdx.y * 128;
    const int bcol = blockIdx.x * 128;

    const int rowA = tid >> 2;           // 0..63 (second: +64)
    const int colA = (tid & 3) * 4;      // 0,4,8,12
    const int rowB = tid >> 5;           // 0..7  (second: +8)
    const int colB = (tid & 31) * 4;     // 0..124

    const float* Ap0 = A + (size_t)(brow + rowA)      * K + colA;
    const float* Ap1 = A + (size_t)(brow + rowA + 64) * K + colA;
    const float* Bp0 = B + (size_t)rowB       * N + bcol + colB;
    const float* Bp1 = B + (size_t)(rowB + 8) * N + bcol + colB;

    float acc[4][4][4];
#pragma unroll
    for (int i = 0; i < 4; ++i)
#pragma unroll
        for (int j = 0; j < 4; ++j)
#pragma unroll
            for (int r = 0; r < 4; ++r) acc[i][j][r] = 0.f;

    const int nk = K >> 4;

    float4 pa0 = *(const float4*)Ap0;
    float4 pa1 = *(const float4*)Ap1;
    float4 pb0 = *(const float4*)Bp0;
    float4 pb1 = *(const float4*)Bp1;

#define GEMM_STORE_STAGE(st)                                             \
    do {                                                                 \
        As[st][colA + 0][rowA]      = f2tf32(pa0.x);                     \
        As[st][colA + 1][rowA]      = f2tf32(pa0.y);                     \
        As[st][colA + 2][rowA]      = f2tf32(pa0.z);                     \
        As[st][colA + 3][rowA]      = f2tf32(pa0.w);                     \
        As[st][colA + 0][rowA + 64] = f2tf32(pa1.x);                     \
        As[st][colA + 1][rowA + 64] = f2tf32(pa1.y);                     \
        As[st][colA + 2][rowA + 64] = f2tf32(pa1.z);                     \
        As[st][colA + 3][rowA + 64] = f2tf32(pa1.w);                     \
        Bs[st][rowB][colB + 0]      = f2tf32(pb0.x);                     \
        Bs[st][rowB][colB + 1]      = f2tf32(pb0.y);                     \
        Bs[st][rowB][colB + 2]      = f2tf32(pb0.z);                     \
        Bs[st][rowB][colB + 3]      = f2tf32(pb0.w);                     \
        Bs[st][rowB + 8][colB + 0]  = f2tf32(pb1.x);                     \
        Bs[st][rowB + 8][colB + 1]  = f2tf32(pb1.y);                     \
        Bs[st][rowB + 8][colB + 2]  = f2tf32(pb1.z);                     \
        Bs[st][rowB + 8][colB + 3]  = f2tf32(pb1.w);                     \
    } while (0)

    // prologue: stage 0 holds t=0; regs hold t=1
    GEMM_STORE_STAGE(0);
    if (nk > 1) {
        pa0 = *(const float4*)(Ap0 + 16);
        pa1 = *(const float4*)(Ap1 + 16);
        pb0 = *(const float4*)(Bp0 + (size_t)16 * N);
        pb1 = *(const float4*)(Bp1 + (size_t)16 * N);
    }
    __syncthreads();

    for (int t = 0; t < nk; ++t) {
        const int cs = t & 1;
        if (t + 1 < nk) {
            GEMM_STORE_STAGE(cs ^ 1);        // regs hold data for t+1
        }
        if (t + 2 < nk) {
            pa0 = *(const float4*)(Ap0 + (size_t)(t + 2) * 16);
            pa1 = *(const float4*)(Ap1 + (size_t)(t + 2) * 16);
            pb0 = *(const float4*)(Bp0 + (size_t)(t + 2) * 16 * N);
            pb1 = *(const float4*)(Bp1 + (size_t)(t + 2) * 16 * N);
        }

#pragma unroll
        for (int ks = 0; ks < 16; ks += 8) {
            uint32_t af[4][4], bf[4][2];
#pragma unroll
            for (int mt = 0; mt < 4; ++mt) {
                int m0 = wm + mt * 16 + grp;
                af[mt][0] = As[cs][ks + qd][m0];
                af[mt][1] = As[cs][ks + qd][m0 + 8];
                af[mt][2] = As[cs][ks + 4 + qd][m0];
                af[mt][3] = As[cs][ks + 4 + qd][m0 + 8];
            }
#pragma unroll
            for (int nt = 0; nt < 4; ++nt) {
                int n0 = wn + nt * 8 + grp;
                bf[nt][0] = Bs[cs][ks + qd][n0];
                bf[nt][1] = Bs[cs][ks + 4 + qd][n0];
            }
#pragma unroll
            for (int mt = 0; mt < 4; ++mt)
#pragma unroll
                for (int nt = 0; nt < 4; ++nt)
                    mma_tf32(acc[mt][nt],
                             af[mt][0], af[mt][1], af[mt][2], af[mt][3],
                             bf[nt][0], bf[nt][1]);
        }
        __syncthreads();
    }

#pragma unroll
    for (int mt = 0; mt < 4; ++mt) {
#pragma unroll
        for (int nt = 0; nt < 4; ++nt) {
            int r = brow + wm + mt * 16 + grp;
            int c = bcol + wn + nt * 8 + 2 * qd;
            float2 lo = {acc[mt][nt][0], acc[mt][nt][1]};
            float2 hi = {acc[mt][nt][2], acc[mt][nt][3]};
            *(float2*)&C[(size_t)r * N + c]       = lo;
            *(float2*)&C[(size_t)(r + 8) * N + c] = hi;
        }
    }
#undef GEMM_STORE_STAGE
}

// =====================================================================
// RoPE, in place. data: [MROWS][heads*128].
// =====================================================================
__global__ void rope_kernel(float* __restrict__ data, int heads, int total)
{
    int idx = blockIdx.x * blockDim.x + threadIdx.x;
    if (idx >= total) return;
    int j   = idx & 63;
    int t2  = idx >> 6;
    int h   = t2 % heads;
    int row = t2 / heads;
    int s   = row & (S_LEN - 1);

    float inv = exp2f((float)j * (-13.287712379549449f / 64.0f));
    float ang = (float)s * inv;
    float sn, cs;
    sincosf(ang, &sn, &cs);

    float* p = data + (size_t)row * heads * HD + (size_t)h * HD;
    float x1 = p[j];
    float x2 = p[j + 64];
    p[j]      = x1 * cs - x2 * sn;
    p[j + 64] = x2 * cs + x1 * sn;
}

// =====================================================================
// Flash attention with tf32 tensor-core MMAs, causal, GQA.
// Grid: (S/64, NH, BATCH). Block: 256 threads (8 warps).
// QK^T: warp tile 16x32 (warps 4x2). PV: warp tile 16x64 (warps 4x2).
// Online softmax stays fp32 in smem.
//   sQ [64][132] tf32 bits, sK [64][132] tf32 bits, sV [64][136] tf32 bits,
//   sP [64][68] fp32, stats 3x64.  (pitches chosen for conflict-free frags)
// =====================================================================
#define AQ_P 132
#define AV_P 136
#define AP_P 68
#define ATTN_SMEM_WORDS (64*AQ_P + 64*AQ_P + 64*AV_P + 64*AP_P + 192)
#define ATTN_SMEM_BYTES (ATTN_SMEM_WORDS * 4)

__global__ __launch_bounds__(256) void attn_mma_kernel(
    const float* __restrict__ Q, const float* __restrict__ K,
    const float* __restrict__ V, float* __restrict__ O)
{
    extern __shared__ uint32_t sm[];
    uint32_t* sQ = sm;                        // [64][132]
    uint32_t* sK = sQ + 64 * AQ_P;            // [64][132]
    uint32_t* sV = sK + 64 * AQ_P;            // [64][136]
    float*    sP = (float*)(sV + 64 * AV_P);  // [64][68]
    float*    rM = sP + 64 * AP_P;
    float*    rL = rM + 64;
    float*    rF = rL + 64;

    const int tid  = threadIdx.x;
    const int lane = tid & 31;
    const int warp = tid >> 5;
    const int grp  = lane >> 2;       // 0..7
    const int qd   = lane & 3;        // 0..3
    const int wr   = warp >> 1;       // 0..3  (m-tile)
    const int wc   = warp & 1;        // 0..1
    const int m0   = wr * 16;

    const int qt = blockIdx.x;
    const int h  = blockIdx.y;
    const int b  = blockIdx.z;
    const int hk = h >> 2;            // GQA repeat_interleave
    const int q0 = qt * 64;

    const size_t qbase  = ((size_t)b * S_LEN + q0) * (NH * HD) + (size_t)h * HD;
    const size_t kvbase = ((size_t)b * S_LEN) * (NKV * HD) + (size_t)hk * HD;

    // ---- load Q tile (cvt to tf32 bits) ----
    for (int f = tid; f < 2048; f += 256) {
        int r = f >> 5;               // 0..63
        int c = (f & 31) * 4;         // 0..124
        float4 v = *(const float4*)(Q + qbase + (size_t)r * (NH * HD) + c);
        uint4 u = {f2tf32(v.x), f2tf32(v.y), f2tf32(v.z), f2tf32(v.w)};
        *(uint4*)&sQ[r * AQ_P + c] = u;
    }
    if (tid < 64) { rM[tid] = -INFINITY; rL[tid] = 0.f; }

    float o_acc[8][4];
#pragma unroll
    for (int i = 0; i < 8; ++i)
#pragma unroll
        for (int j = 0; j < 4; ++j) o_acc[i][j] = 0.f;

    const float scale = 0.08838834764831845f;  // 1/sqrt(128)
    const int ntiles = qt + 1;

    for (int t = 0; t < ntiles; ++t) {
        const int k0 = t * 64;
        __syncthreads();  // prev PV done (covers Q/stats init at t=0)

        // ---- load K, V tiles ----
        for (int f = tid; f < 2048; f += 256) {
            int r = f >> 5, c = (f & 31) * 4;
            float4 v = *(const float4*)(K + kvbase + (size_t)(k0 + r) * (NKV * HD) + c);
            uint4 u = {f2tf32(v.x), f2tf32(v.y), f2tf32(v.z), f2tf32(v.w)};
            *(uint4*)&sK[r * AQ_P + c] = u;
        }
        for (int f = tid; f < 2048; f += 256) {
            int r = f >> 5, c = (f & 31) * 4;
            float4 v = *(const float4*)(V + kvbase + (size_t)(k0 + r) * (NKV * HD) + c);
            uint4 u = {f2tf32(v.x), f2tf32(v.y), f2tf32(v.z), f2tf32(v.w)};
            *(uint4*)&sV[r * AV_P + c] = u;
        }
        __syncthreads();

        // ---- S = Q @ K^T : warp tile 16x32, K-dim 128 (16 mma k-steps) ----
        float s_acc[4][4];
#pragma unroll
        for (int nt = 0; nt < 4; ++nt)
#pragma unroll
            for (int r = 0; r < 4; ++r) s_acc[nt][r] = 0.f;

#pragma unroll
        for (int ks = 0; ks < 16; ++ks) {
            const int kk = ks * 8;
            uint32_t a0 = sQ[(m0 + grp)     * AQ_P + kk + qd];
            uint32_t a1 = sQ[(m0 + grp + 8) * AQ_P + kk + qd];
            uint32_t a2 = sQ[(m0 + grp)     * AQ_P + kk + qd + 4];
            uint32_t a3 = sQ[(m0 + grp + 8) * AQ_P + kk + qd + 4];
#pragma unroll
            for (int nt = 0; nt < 4; ++nt) {
                int n = wc * 32 + nt * 8 + grp;
                uint32_t b0 = sK[n * AQ_P + kk + qd];
                uint32_t b1 = sK[n * AQ_P + kk + qd + 4];
                mma_tf32(s_acc[nt], a0, a1, a2, a3, b0, b1);
            }
        }

        // ---- write S to sP with scale + causal mask ----
        const bool dg = (k0 == q0);
        const int r0 = m0 + grp, r1 = m0 + grp + 8;
#pragma unroll
        for (int nt = 0; nt < 4; ++nt) {
            int nc = wc * 32 + nt * 8 + 2 * qd;
            float v0 = s_acc[nt][0] * scale;
            float v1 = s_acc[nt][1] * scale;
            float v2 = s_acc[nt][2] * scale;
            float v3 = s_acc[nt][3] * scale;
            if (dg) {
                if (nc     > r0) v0 = -INFINITY;
                if (nc + 1 > r0) v1 = -INFINITY;
                if (nc     > r1) v2 = -INFINITY;
                if (nc + 1 > r1) v3 = -INFINITY;
            }
            sP[r0 * AP_P + nc]     = v0;
            sP[r0 * AP_P + nc + 1] = v1;
            sP[r1 * AP_P + nc]     = v2;
            sP[r1 * AP_P + nc + 1] = v3;
        }
        __syncthreads();

        // ---- online softmax: 4 threads per row, 16 cols each ----
        {
            int row = tid >> 2, seg = tid & 3;
            float* pr = &sP[row * AP_P + seg * 16];
            float m_old = rM[row];
            float ml = -INFINITY;
#pragma unroll
            for (int i = 0; i < 16; ++i) ml = fmaxf(ml, pr[i]);
            ml = fmaxf(ml, __shfl_xor_sync(0xffffffffu, ml, 1));
            ml = fmaxf(ml, __shfl_xor_sync(0xffffffffu, ml, 2));
            float m_new = fmaxf(m_old, ml);
            float ls = 0.f;
#pragma unroll
            for (int i = 0; i < 16; ++i) {
                float p = __expf(pr[i] - m_new);
                pr[i] = p;
                ls += p;
            }
            ls += __shfl_xor_sync(0xffffffffu, ls, 1);
            ls += __shfl_xor_sync(0xffffffffu, ls, 2);
            if (seg == 0) {
                float fac = __expf(m_old - m_new);
                rF[row] = fac;
                rL[row] = rL[row] * fac + ls;
                rM[row] = m_new;
            }
        }
        __syncthreads();

        // ---- rescale O, accumulate O += P @ V : warp tile 16x64, K=64 ----
        const float fr0 = rF[m0 + grp];
        const float fr1 = rF[m0 + grp + 8];
#pragma unroll
        for (int nt = 0; nt < 8; ++nt) {
            o_acc[nt][0] *= fr0; o_acc[nt][1] *= fr0;
            o_acc[nt][2] *= fr1; o_acc[nt][3] *= fr1;
        }

#pragma unroll
        for (int ks = 0; ks < 8; ++ks) {
            const int kk = ks * 8;
            uint32_t a0 = f2tf32(sP[(m0 + grp)     * AP_P + kk + qd]);
            uint32_t a1 = f2tf32(sP[(m0 + grp + 8) * AP_P + kk + qd]);
            uint32_t a2 = f2tf32(sP[(m0 + grp)     * AP_P + kk + qd + 4]);
            uint32_t a3 = f2tf32(sP[(m0 + grp + 8) * AP_P + kk + qd + 4]);
#pragma unroll
            for (int nt = 0; nt < 8; ++nt) {
                int n = wc * 64 + nt * 8 + grp;
                uint32_t b0 = sV[(kk + qd)     * AV_P + n];
                uint32_t b1 = sV[(kk + qd + 4) * AV_P + n];
                mma_tf32(o_acc[nt], a0, a1, a2, a3, b0, b1);
            }
        }
    }

    // ---- normalize, write out ----
    const float inv0 = 1.f / rL[m0 + grp];
    const float inv1 = 1.f / rL[m0 + grp + 8];
    const size_t ro0 = ((size_t)b * S_LEN + q0 + m0 + grp)     * DIM_ + (size_t)h * HD;
    const size_t ro1 = ((size_t)b * S_LEN + q0 + m0 + grp + 8) * DIM_ + (size_t)h * HD;
#pragma unroll
    for (int nt = 0; nt < 8; ++nt) {
        int c = wc * 64 + nt * 8 + 2 * qd;
        float2 lo = {o_acc[nt][0] * inv0, o_acc[nt][1] * inv0};
        float2 hi = {o_acc[nt][2] * inv1, o_acc[nt][3] * inv1};
        *(float2*)&O[ro0 + c] = lo;
        *(float2*)&O[ro1 + c] = hi;
    }
}

// =====================================================================
// kernel_launch: x, wq, wk, wv, wo  (metadata order)
// =====================================================================
extern "C" void kernel_launch(void* const* d_in, const int* in_sizes, int n_in,
                              void* d_out, int out_size)
{
    const float* x  = (const float*)d_in[0];
    const float* wq = (const float*)d_in[1];
    const float* wk = (const float*)d_in[2];
    const float* wv = (const float*)d_in[3];
    const float* wo = (const float*)d_in[4];
    float* out = (float*)d_out;

    float *q, *k, *v, *attn;
    cudaGetSymbolAddress((void**)&q,    g_q);
    cudaGetSymbolAddress((void**)&k,    g_k);
    cudaGetSymbolAddress((void**)&v,    g_v);
    cudaGetSymbolAddress((void**)&attn, g_attn);

    // QKV projections (tf32 tensor cores, ping-pong pipelined)
    gemm_tf32<<<dim3(DIM_ / 128, MROWS / 128), 256>>>(x, wq, q, MROWS, DIM_, DIM_);
    gemm_tf32<<<dim3((NKV * HD) / 128, MROWS / 128), 256>>>(x, wk, k, MROWS, NKV * HD, DIM_);
    gemm_tf32<<<dim3((NKV * HD) / 128, MROWS / 128), 256>>>(x, wv, v, MROWS, NKV * HD, DIM_);

    // RoPE on Q and K
    {
        int totq = MROWS * NH * 64;
        rope_kernel<<<(totq + 255) / 256, 256>>>(q, NH, totq);
        int totk = MROWS * NKV * 64;
        rope_kernel<<<(totk + 255) / 256, 256>>>(k, NKV, totk);
    }

    // Flash attention (tf32 tensor cores)
    cudaFuncSetAttribute(attn_mma_kernel, cudaFuncAttributeMaxDynamicSharedMemorySize,
                         ATTN_SMEM_BYTES);
    attn_mma_kernel<<<dim3(S_LEN / 64, NH, BATCH), 256, ATTN_SMEM_BYTES>>>(q, k, v, attn);

    // Output projection
    gemm_tf32<<<dim3(DIM_ / 128, MROWS / 128), 256>>>(attn, wo, out, MROWS, DIM_, DIM_);
}

// round 16
// speedup vs baseline: 1.1314x; 1.1290x over previous
#include <cuda_runtime.h>
#include <math.h>
#include <stdint.h>

// ---------------- problem constants ----------------
#define S_LEN   2048
#define BATCH   2
#define DIM_    2048
#define NH      16
#define NKV     4
#define HD      128
#define MROWS   (BATCH * S_LEN)      // 4096

// ---------------- device scratch (static, allocation-free) ----------------
__device__ float g_q[(size_t)MROWS * NH * HD];      // [4096][2048]
__device__ float g_k[(size_t)MROWS * NKV * HD];     // [4096][512]
__device__ float g_v[(size_t)MROWS * NKV * HD];     // [4096][512]
__device__ float g_attn[(size_t)MROWS * DIM_];      // [4096][2048]

// ---------------- tf32 helpers ----------------
__device__ __forceinline__ uint32_t f2tf32(float x) {
    uint32_t r;
    asm("cvt.rna.tf32.f32 %0, %1;" : "=r"(r) : "f"(x));
    return r;
}

__device__ __forceinline__ void mma_tf32(float c[4],
    uint32_t a0, uint32_t a1, uint32_t a2, uint32_t a3,
    uint32_t b0, uint32_t b1)
{
    asm volatile(
        "mma.sync.aligned.m16n8k8.row.col.f32.tf32.tf32.f32 "
        "{%0,%1,%2,%3}, {%4,%5,%6,%7}, {%8,%9}, {%0,%1,%2,%3};"
        : "+f"(c[0]), "+f"(c[1]), "+f"(c[2]), "+f"(c[3])
        : "r"(a0), "r"(a1), "r"(a2), "r"(a3), "r"(b0), "r"(b1));
}

// =====================================================================
// TF32 tensor-core GEMM, ping-pong double-buffered smem (1 sync/iter).
// =====================================================================
#define SMS 132

__global__ __launch_bounds__(256, 2) void gemm_tf32(
    const float* __restrict__ A, const float* __restrict__ B,
    float* __restrict__ C, int M, int N, int K)
{
    __shared__ uint32_t As[2][16][SMS];
    __shared__ uint32_t Bs[2][16][SMS];

    const int tid  = threadIdx.x;
    const int lane = tid & 31;
    const int warp = tid >> 5;
    const int wm   = (warp >> 2) * 64;
    const int wn   = (warp & 3) * 32;
    const int grp  = lane >> 2;
    const int qd   = lane & 3;

    const int brow = blockIdx.y * 128;
    const int bcol = blockIdx.x * 128;

    const int rowA = tid >> 2;
    const int colA = (tid & 3) * 4;
    const int rowB = tid >> 5;
    const int colB = (tid & 31) * 4;

    const float* Ap0 = A + (size_t)(brow + rowA)      * K + colA;
    const float* Ap1 = A + (size_t)(brow + rowA + 64) * K + colA;
    const float* Bp0 = B + (size_t)rowB       * N + bcol + colB;
    const float* Bp1 = B + (size_t)(rowB + 8) * N + bcol + colB;

    float acc[4][4][4];
#pragma unroll
    for (int i = 0; i < 4; ++i)
#pragma unroll
        for (int j = 0; j < 4; ++j)
#pragma unroll
            for (int r = 0; r < 4; ++r) acc[i][j][r] = 0.f;

    const int nk = K >> 4;

    float4 pa0 = *(const float4*)Ap0;
    float4 pa1 = *(const float4*)Ap1;
    float4 pb0 = *(const float4*)Bp0;
    float4 pb1 = *(const float4*)Bp1;

#define GEMM_STORE_STAGE(st)                                             \
    do {                                                                 \
        As[st][colA + 0][rowA]      = f2tf32(pa0.x);                     \
        As[st][colA + 1][rowA]      = f2tf32(pa0.y);                     \
        As[st][colA + 2][rowA]      = f2tf32(pa0.z);                     \
        As[st][colA + 3][rowA]      = f2tf32(pa0.w);                     \
        As[st][colA + 0][rowA + 64] = f2tf32(pa1.x);                     \
        As[st][colA + 1][rowA + 64] = f2tf32(pa1.y);                     \
        As[st][colA + 2][rowA + 64] = f2tf32(pa1.z);                     \
        As[st][colA + 3][rowA + 64] = f2tf32(pa1.w);                     \
        Bs[st][rowB][colB + 0]      = f2tf32(pb0.x);                     \
        Bs[st][rowB][colB + 1]      = f2tf32(pb0.y);                     \
        Bs[st][rowB][colB + 2]      = f2tf32(pb0.z);                     \
        Bs[st][rowB][colB + 3]      = f2tf32(pb0.w);                     \
        Bs[st][rowB + 8][colB + 0]  = f2tf32(pb1.x);                     \
        Bs[st][rowB + 8][colB + 1]  = f2tf32(pb1.y);                     \
        Bs[st][rowB + 8][colB + 2]  = f2tf32(pb1.z);                     \
        Bs[st][rowB + 8][colB + 3]  = f2tf32(pb1.w);                     \
    } while (0)

    GEMM_STORE_STAGE(0);
    if (nk > 1) {
        pa0 = *(const float4*)(Ap0 + 16);
        pa1 = *(const float4*)(Ap1 + 16);
        pb0 = *(const float4*)(Bp0 + (size_t)16 * N);
        pb1 = *(const float4*)(Bp1 + (size_t)16 * N);
    }
    __syncthreads();

    for (int t = 0; t < nk; ++t) {
        const int cs = t & 1;
        if (t + 1 < nk) {
            GEMM_STORE_STAGE(cs ^ 1);
        }
        if (t + 2 < nk) {
            pa0 = *(const float4*)(Ap0 + (size_t)(t + 2) * 16);
            pa1 = *(const float4*)(Ap1 + (size_t)(t + 2) * 16);
            pb0 = *(const float4*)(Bp0 + (size_t)(t + 2) * 16 * N);
            pb1 = *(const float4*)(Bp1 + (size_t)(t + 2) * 16 * N);
        }

#pragma unroll
        for (int ks = 0; ks < 16; ks += 8) {
            uint32_t af[4][4], bf[4][2];
#pragma unroll
            for (int mt = 0; mt < 4; ++mt) {
                int m0 = wm + mt * 16 + grp;
                af[mt][0] = As[cs][ks + qd][m0];
                af[mt][1] = As[cs][ks + qd][m0 + 8];
                af[mt][2] = As[cs][ks + 4 + qd][m0];
                af[mt][3] = As[cs][ks + 4 + qd][m0 + 8];
            }
#pragma unroll
            for (int nt = 0; nt < 4; ++nt) {
                int n0 = wn + nt * 8 + grp;
                bf[nt][0] = Bs[cs][ks + qd][n0];
                bf[nt][1] = Bs[cs][ks + 4 + qd][n0];
            }
#pragma unroll
            for (int mt = 0; mt < 4; ++mt)
#pragma unroll
                for (int nt = 0; nt < 4; ++nt)
                    mma_tf32(acc[mt][nt],
                             af[mt][0], af[mt][1], af[mt][2], af[mt][3],
                             bf[nt][0], bf[nt][1]);
        }
        __syncthreads();
    }

#pragma unroll
    for (int mt = 0; mt < 4; ++mt) {
#pragma unroll
        for (int nt = 0; nt < 4; ++nt) {
            int r = brow + wm + mt * 16 + grp;
            int c = bcol + wn + nt * 8 + 2 * qd;
            float2 lo = {acc[mt][nt][0], acc[mt][nt][1]};
            float2 hi = {acc[mt][nt][2], acc[mt][nt][3]};
            *(float2*)&C[(size_t)r * N + c]       = lo;
            *(float2*)&C[(size_t)(r + 8) * N + c] = hi;
        }
    }
#undef GEMM_STORE_STAGE
}

// =====================================================================
// RoPE, in place. data: [MROWS][heads*128].
// =====================================================================
__global__ void rope_kernel(float* __restrict__ data, int heads, int total)
{
    int idx = blockIdx.x * blockDim.x + threadIdx.x;
    if (idx >= total) return;
    int j   = idx & 63;
    int t2  = idx >> 6;
    int h   = t2 % heads;
    int row = t2 / heads;
    int s   = row & (S_LEN - 1);

    float inv = exp2f((float)j * (-13.287712379549449f / 64.0f));
    float ang = (float)s * inv;
    float sn, cs;
    sincosf(ang, &sn, &cs);

    float* p = data + (size_t)row * heads * HD + (size_t)h * HD;
    float x1 = p[j];
    float x2 = p[j + 64];
    p[j]      = x1 * cs - x2 * sn;
    p[j + 64] = x2 * cs + x1 * sn;
}

// =====================================================================
// Flash attention v2: tf32 MMA, register softmax, 2 syncs/tile.
// Grid: (S/128, NH, BATCH). Block: 256 threads (8 warps).
// Each warp owns 16 q-rows exclusively (warp tile QK 16x64, PV 16x128).
// Q tile 128x128 in smem (pre-scaled tf32), K/V tiles 64x128,
// register-prefetched LDG, P kept in registers (quad-shuffle to A-frags).
//   sQ [128][132], sK [64][132], sV [64][136] (tf32 bits)
// =====================================================================
#define AQ_P 132
#define AV_P 136
#define A2_SQ_W   (128 * AQ_P)
#define A2_SK_W   (64 * AQ_P)
#define A2_SV_W   (64 * AV_P)
#define ATTN2_SMEM_BYTES ((A2_SQ_W + A2_SK_W + A2_SV_W) * 4)

__global__ __launch_bounds__(256) void attn_mma2_kernel(
    const float* __restrict__ Q, const float* __restrict__ K,
    const float* __restrict__ V, float* __restrict__ O)
{
    extern __shared__ uint32_t sm[];
    uint32_t* sQ = sm;                    // [128][132]
    uint32_t* sK = sQ + A2_SQ_W;          // [64][132]
    uint32_t* sV = sK + A2_SK_W;          // [64][136]

    const int tid  = threadIdx.x;
    const int lane = tid & 31;
    const int warp = tid >> 5;            // 0..7
    const int grp  = lane >> 2;           // 0..7
    const int qd   = lane & 3;            // 0..3
    const int m0   = warp * 16;           // warp's q-row offset in tile

    const int qt = gridDim.x - 1 - blockIdx.x;   // heavy blocks first
    const int h  = blockIdx.y;
    const int b  = blockIdx.z;
    const int hk = h >> 2;                // GQA repeat_interleave
    const int q0 = qt * 128;

    const size_t qbase  = ((size_t)b * S_LEN + q0) * (NH * HD) + (size_t)h * HD;
    const size_t kvbase = ((size_t)b * S_LEN) * (NKV * HD) + (size_t)hk * HD;
    const float scale = 0.08838834764831845f;    // 1/sqrt(128)

    // ---- load Q tile, pre-scaled, tf32 bits: 16 float4 per thread ----
#pragma unroll
    for (int i = 0; i < 16; ++i) {
        int r = warp + 8 * i;             // 0..127
        int c = lane * 4;                 // 0..124
        float4 v = *(const float4*)(Q + qbase + (size_t)r * (NH * HD) + c);
        uint4 u = {f2tf32(v.x * scale), f2tf32(v.y * scale),
                   f2tf32(v.z * scale), f2tf32(v.w * scale)};
        *(uint4*)&sQ[r * AQ_P + c] = u;
    }

    // per-thread softmax state (rows m0+grp and m0+grp+8)
    float st_m0 = -INFINITY, st_m1 = -INFINITY;
    float st_l0 = 0.f, st_l1 = 0.f;

    float o_acc[16][4];
#pragma unroll
    for (int i = 0; i < 16; ++i)
#pragma unroll
        for (int j = 0; j < 4; ++j) o_acc[i][j] = 0.f;

    const int ntiles = 2 * qt + 2;
    const int kvstep = NKV * HD;          // 512

    // prologue: prefetch K(0)
    float4 kreg[8];
#pragma unroll
    for (int i = 0; i < 8; ++i)
        kreg[i] = *(const float4*)(K + kvbase + (size_t)(warp + 8 * i) * kvstep + lane * 4);

    for (int t = 0; t < ntiles; ++t) {
        const int k0 = t * 64;

        // ---- store K(t) regs -> sK ----
#pragma unroll
        for (int i = 0; i < 8; ++i) {
            int r = warp + 8 * i;
            uint4 u = {f2tf32(kreg[i].x), f2tf32(kreg[i].y),
                       f2tf32(kreg[i].z), f2tf32(kreg[i].w)};
            *(uint4*)&sK[r * AQ_P + lane * 4] = u;
        }
        // ---- issue LDG V(t) ----
        float4 vreg[8];
#pragma unroll
        for (int i = 0; i < 8; ++i)
            vreg[i] = *(const float4*)(V + kvbase + (size_t)(k0 + warp + 8 * i) * kvstep + lane * 4);

        __syncthreads();   // K visible; prev PV complete (sV writable)

        const bool active = (k0 <= q0 + m0 + 15);
        float s_acc[8][4];

        // ---- QK^T : warp tile 16x64, K-dim 128 ----
        if (active) {
#pragma unroll
            for (int nt = 0; nt < 8; ++nt)
#pragma unroll
                for (int r = 0; r < 4; ++r) s_acc[nt][r] = 0.f;

#pragma unroll
            for (int ks = 0; ks < 16; ++ks) {
                const int kk = ks * 8;
                uint32_t a0 = sQ[(m0 + grp)     * AQ_P + kk + qd];
                uint32_t a1 = sQ[(m0 + grp + 8) * AQ_P + kk + qd];
                uint32_t a2 = sQ[(m0 + grp)     * AQ_P + kk + qd + 4];
                uint32_t a3 = sQ[(m0 + grp + 8) * AQ_P + kk + qd + 4];
#pragma unroll
                for (int nt = 0; nt < 8; ++nt) {
                    int n = nt * 8 + grp;
                    uint32_t b0 = sK[n * AQ_P + kk + qd];
                    uint32_t b1 = sK[n * AQ_P + kk + qd + 4];
                    mma_tf32(s_acc[nt], a0, a1, a2, a3, b0, b1);
                }
            }
        }

        // ---- store V(t) regs -> sV ----
#pragma unroll
        for (int i = 0; i < 8; ++i) {
            int r = warp + 8 * i;
            uint4 u = {f2tf32(vreg[i].x), f2tf32(vreg[i].y),
                       f2tf32(vreg[i].z), f2tf32(vreg[i].w)};
            *(uint4*)&sV[r * AV_P + lane * 4] = u;
        }
        // ---- issue LDG K(t+1) ----
        if (t + 1 < ntiles) {
#pragma unroll
            for (int i = 0; i < 8; ++i)
                kreg[i] = *(const float4*)(K + kvbase + (size_t)(k0 + 64 + warp + 8 * i) * kvstep + lane * 4);
        }

        // ---- mask + online softmax, all in registers ----
        if (active) {
            const int r0g = q0 + m0 + grp;
            const int r1g = r0g + 8;
            if (k0 + 63 > q0 + m0) {      // diagonal-ish tile: elementwise mask
#pragma unroll
                for (int nt = 0; nt < 8; ++nt) {
                    int c = k0 + nt * 8 + 2 * qd;
                    if (c     > r0g) s_acc[nt][0] = -INFINITY;
                    if (c + 1 > r0g) s_acc[nt][1] = -INFINITY;
                    if (c     > r1g) s_acc[nt][2] = -INFINITY;
                    if (c + 1 > r1g) s_acc[nt][3] = -INFINITY;
                }
            }
            float ml0 = -INFINITY, ml1 = -INFINITY;
#pragma unroll
            for (int nt = 0; nt < 8; ++nt) {
                ml0 = fmaxf(ml0, fmaxf(s_acc[nt][0], s_acc[nt][1]));
                ml1 = fmaxf(ml1, fmaxf(s_acc[nt][2], s_acc[nt][3]));
            }
            ml0 = fmaxf(ml0, __shfl_xor_sync(0xffffffffu, ml0, 1));
            ml0 = fmaxf(ml0, __shfl_xor_sync(0xffffffffu, ml0, 2));
            ml1 = fmaxf(ml1, __shfl_xor_sync(0xffffffffu, ml1, 1));
            ml1 = fmaxf(ml1, __shfl_xor_sync(0xffffffffu, ml1, 2));
            float mn0 = fmaxf(st_m0, ml0);
            float mn1 = fmaxf(st_m1, ml1);
            float ls0 = 0.f, ls1 = 0.f;
#pragma unroll
            for (int nt = 0; nt < 8; ++nt) {
                s_acc[nt][0] = __expf(s_acc[nt][0] - mn0);
                s_acc[nt][1] = __expf(s_acc[nt][1] - mn0);
                s_acc[nt][2] = __expf(s_acc[nt][2] - mn1);
                s_acc[nt][3] = __expf(s_acc[nt][3] - mn1);
                ls0 += s_acc[nt][0] + s_acc[nt][1];
                ls1 += s_acc[nt][2] + s_acc[nt][3];
            }
            ls0 += __shfl_xor_sync(0xffffffffu, ls0, 1);
            ls0 += __shfl_xor_sync(0xffffffffu, ls0, 2);
            ls1 += __shfl_xor_sync(0xffffffffu, ls1, 1);
            ls1 += __shfl_xor_sync(0xffffffffu, ls1, 2);
            float fac0 = __expf(st_m0 - mn0);   // 0 on first tile
            float fac1 = __expf(st_m1 - mn1);
            st_l0 = st_l0 * fac0 + ls0;
            st_l1 = st_l1 * fac1 + ls1;
            st_m0 = mn0;
            st_m1 = mn1;
#pragma unroll
            for (int nt = 0; nt < 16; ++nt) {
                o_acc[nt][0] *= fac0; o_acc[nt][1] *= fac0;
                o_acc[nt][2] *= fac1; o_acc[nt][3] *= fac1;
            }
        }

        __syncthreads();   // V visible; QK done for all (sK writable next iter)

        // ---- PV : warp tile 16x128, K-dim 64; P shuffled into A-frags ----
        if (active) {
            const int src0 = (lane & ~3) | (qd >> 1);
            const int src1 = src0 + 2;
            const int e = qd & 1;
#pragma unroll
            for (int ks = 0; ks < 8; ++ks) {
                const int kk = ks * 8;
                float p0 = __shfl_sync(0xffffffffu, s_acc[ks][0], src0);
                float p1 = __shfl_sync(0xffffffffu, s_acc[ks][1], src0);
                float p2 = __shfl_sync(0xffffffffu, s_acc[ks][2], src0);
                float p3 = __shfl_sync(0xffffffffu, s_acc[ks][3], src0);
                float q0f = __shfl_sync(0xffffffffu, s_acc[ks][0], src1);
                float q1f = __shfl_sync(0xffffffffu, s_acc[ks][1], src1);
                float q2f = __shfl_sync(0xffffffffu, s_acc[ks][2], src1);
                float q3f = __shfl_sync(0xffffffffu, s_acc[ks][3], src1);
                uint32_t a0 = f2tf32(e ? p1 : p0);
                uint32_t a1 = f2tf32(e ? p3 : p2);
                uint32_t a2 = f2tf32(e ? q1f : q0f);
                uint32_t a3 = f2tf32(e ? q3f : q2f);
#pragma unroll
                for (int nt = 0; nt < 16; ++nt) {
                    int n = nt * 8 + grp;
                    uint32_t b0 = sV[(kk + qd)     * AV_P + n];
                    uint32_t b1 = sV[(kk + qd + 4) * AV_P + n];
                    mma_tf32(o_acc[nt], a0, a1, a2, a3, b0, b1);
                }
            }
        }
    }

    // ---- normalize, write out ----
    const float inv0 = 1.f / st_l0;
    const float inv1 = 1.f / st_l1;
    const size_t ro0 = ((size_t)b * S_LEN + q0 + m0 + grp)     * DIM_ + (size_t)h * HD;
    const size_t ro1 = ((size_t)b * S_LEN + q0 + m0 + grp + 8) * DIM_ + (size_t)h * HD;
#pragma unroll
    for (int nt = 0; nt < 16; ++nt) {
        int c = nt * 8 + 2 * qd;
        float2 lo = {o_acc[nt][0] * inv0, o_acc[nt][1] * inv0};
        float2 hi = {o_acc[nt][2] * inv1, o_acc[nt][3] * inv1};
        *(float2*)&O[ro0 + c] = lo;
        *(float2*)&O[ro1 + c] = hi;
    }
}

// =====================================================================
// kernel_launch: x, wq, wk, wv, wo  (metadata order)
// =====================================================================
extern "C" void kernel_launch(void* const* d_in, const int* in_sizes, int n_in,
                              void* d_out, int out_size)
{
    const float* x  = (const float*)d_in[0];
    const float* wq = (const float*)d_in[1];
    const float* wk = (const float*)d_in[2];
    const float* wv = (const float*)d_in[3];
    const float* wo = (const float*)d_in[4];
    float* out = (float*)d_out;

    float *q, *k, *v, *attn;
    cudaGetSymbolAddress((void**)&q,    g_q);
    cudaGetSymbolAddress((void**)&k,    g_k);
    cudaGetSymbolAddress((void**)&v,    g_v);
    cudaGetSymbolAddress((void**)&attn, g_attn);

    // QKV projections (tf32 tensor cores, ping-pong pipelined)
    gemm_tf32<<<dim3(DIM_ / 128, MROWS / 128), 256>>>(x, wq, q, MROWS, DIM_, DIM_);
    gemm_tf32<<<dim3((NKV * HD) / 128, MROWS / 128), 256>>>(x, wk, k, MROWS, NKV * HD, DIM_);
    gemm_tf32<<<dim3((NKV * HD) / 128, MROWS / 128), 256>>>(x, wv, v, MROWS, NKV * HD, DIM_);

    // RoPE on Q and K
    {
        int totq = MROWS * NH * 64;
        rope_kernel<<<(totq + 255) / 256, 256>>>(q, NH, totq);
        int totk = MROWS * NKV * 64;
        rope_kernel<<<(totk + 255) / 256, 256>>>(k, NKV, totk);
    }

    // Flash attention v2 (register softmax, 2 syncs/tile)
    cudaFuncSetAttribute(attn_mma2_kernel, cudaFuncAttributeMaxDynamicSharedMemorySize,
                         ATTN2_SMEM_BYTES);
    attn_mma2_kernel<<<dim3(S_LEN / 128, NH, BATCH), 256, ATTN2_SMEM_BYTES>>>(q, k, v, attn);

    // Output projection
    gemm_tf32<<<dim3(DIM_ / 128, MROWS / 128), 256>>>(attn, wo, out, MROWS, DIM_, DIM_);
}